// round 2
// baseline (speedup 1.0000x reference)
#include <cuda_runtime.h>
#include <math.h>

#define BB 2
#define TT 2048
#define CC 1024
#define HH 16
#define DD 64
#define MROWS (BB*TT)   // 4096

// Scratch (allocation-free rule: __device__ globals)
__device__ float g_Q[BB*HH*TT*DD];   // [B,H,T,D]
__device__ float g_K[BB*HH*TT*DD];
__device__ float g_V[BB*HH*TT*DD];
__device__ float g_Y[BB*TT*CC];      // attention output, [B,T,C]

// ---------------------------------------------------------------------------
// GEMM: out[m,n] = sum_k A[m,k] * W[n,k] + bias[n]
// MODE 0: scatter into g_Q/g_K/g_V ([B,H,T,D]);  MODE 1: write out[m*N+n]
// BM=BN=64, BK=16, 256 threads, 4x4 per thread.
// ---------------------------------------------------------------------------
template<int MODE, int NDIM, int KDIM>
__global__ void gemm_bias_kernel(const float* __restrict__ A,
                                 const float* __restrict__ W,
                                 const float* __restrict__ bias,
                                 float* __restrict__ out)
{
    const int BM = 64, BN = 64, BK = 16;
    __shared__ float As[BK][BM + 4];
    __shared__ float Bs[BK][BN + 4];

    const int bm = blockIdx.y * BM;
    const int bn = blockIdx.x * BN;
    const int tid = threadIdx.x;
    const int tx = tid & 15;
    const int ty = tid >> 4;

    const float* Ap = (MODE == 0) ? A : g_Y;

    float acc[4][4];
#pragma unroll
    for (int i = 0; i < 4; i++)
#pragma unroll
        for (int j = 0; j < 4; j++) acc[i][j] = 0.0f;

    for (int k0 = 0; k0 < KDIM; k0 += BK) {
#pragma unroll
        for (int p = 0; p < 4; p++) {
            int r = (tid >> 4) + p * 16;  // 0..63
            int c = tid & 15;             // 0..15
            As[c][r] = Ap[(size_t)(bm + r) * KDIM + k0 + c];
            Bs[c][r] = W [(size_t)(bn + r) * KDIM + k0 + c];
        }
        __syncthreads();
#pragma unroll
        for (int k = 0; k < BK; k++) {
            float a[4], b[4];
#pragma unroll
            for (int i = 0; i < 4; i++) a[i] = As[k][ty * 4 + i];
#pragma unroll
            for (int j = 0; j < 4; j++) b[j] = Bs[k][tx * 4 + j];
#pragma unroll
            for (int i = 0; i < 4; i++)
#pragma unroll
                for (int j = 0; j < 4; j++) acc[i][j] += a[i] * b[j];
        }
        __syncthreads();
    }

#pragma unroll
    for (int i = 0; i < 4; i++) {
#pragma unroll
        for (int j = 0; j < 4; j++) {
            int m = bm + ty * 4 + i;
            int n = bn + tx * 4 + j;
            float v = acc[i][j] + bias[n];
            if (MODE == 0) {
                int part = n / CC;
                int c    = n - part * CC;
                int h    = c >> 6;      // c / 64
                int d    = c & 63;
                int b_   = m / TT;
                int t    = m - b_ * TT;
                int idx  = ((b_ * HH + h) * TT + t) * DD + d;
                if (part == 0)      g_Q[idx] = v;
                else if (part == 1) g_K[idx] = v;
                else                g_V[idx] = v;
            } else {
                out[(size_t)m * NDIM + n] = v;
            }
        }
    }
}

// ---------------------------------------------------------------------------
// Flash attention, fp32, causal. One block per (q-tile 64, b*H).
// 256 threads (16x16), each owns a 4x4 microtile of S and of O.
// Row softmax reductions via shfl within 16-lane groups (same ty == same half-warp).
// ---------------------------------------------------------------------------
__global__ void flash_kernel(float* __restrict__ Yout)
{
    extern __shared__ float sm[];
    const int LD = 68;                 // row pitch (floats)
    float* Qs = sm;                    // 64 x 68
    float* Ks = Qs + 64 * LD;
    float* Vs = Ks + 64 * LD;
    float* Ps = Vs + 64 * LD;

    const int qt = blockIdx.x;         // 0..31
    const int bh = blockIdx.y;         // 0..31  (= b*H + h)
    const int b_ = bh / HH;
    const int h  = bh % HH;
    const int q0 = qt * 64;

    const float* Qg = g_Q + (size_t)bh * TT * DD;
    const float* Kg = g_K + (size_t)bh * TT * DD;
    const float* Vg = g_V + (size_t)bh * TT * DD;

    const int tid = threadIdx.x;
    const int tx = tid & 15;
    const int ty = tid >> 4;
    const float scale = 0.125f;        // 1/sqrt(64)

    // Load Q tile [64 x 64]
#pragma unroll
    for (int p = 0; p < 16; p++) {
        int idx = tid + p * 256;
        int r = idx >> 6;
        int c = idx & 63;
        Qs[r * LD + c] = Qg[(size_t)(q0 + r) * DD + c];
    }

    float m_i[4], l_i[4], O[4][4];
#pragma unroll
    for (int i = 0; i < 4; i++) {
        m_i[i] = -INFINITY;
        l_i[i] = 0.0f;
#pragma unroll
        for (int j = 0; j < 4; j++) O[i][j] = 0.0f;
    }

    for (int kt = 0; kt <= qt; kt++) {
        const int k0 = kt * 64;
        __syncthreads();   // previous iteration done with Ks/Vs/Ps
#pragma unroll
        for (int p = 0; p < 16; p++) {
            int idx = tid + p * 256;
            int r = idx >> 6;
            int c = idx & 63;
            Ks[r * LD + c] = Kg[(size_t)(k0 + r) * DD + c];
            Vs[r * LD + c] = Vg[(size_t)(k0 + r) * DD + c];
        }
        __syncthreads();

        // S = scale * Q K^T for this 64x64 tile (4x4 per thread)
        float s[4][4];
#pragma unroll
        for (int i = 0; i < 4; i++)
#pragma unroll
            for (int j = 0; j < 4; j++) s[i][j] = 0.0f;

#pragma unroll 8
        for (int d = 0; d < 64; d++) {
            float a[4], bb[4];
#pragma unroll
            for (int i = 0; i < 4; i++) a[i]  = Qs[(ty * 4 + i) * LD + d];
#pragma unroll
            for (int j = 0; j < 4; j++) bb[j] = Ks[(tx * 4 + j) * LD + d];
#pragma unroll
            for (int i = 0; i < 4; i++)
#pragma unroll
                for (int j = 0; j < 4; j++) s[i][j] += a[i] * bb[j];
        }

        const bool diag = (kt == qt);
#pragma unroll
        for (int i = 0; i < 4; i++)
#pragma unroll
            for (int j = 0; j < 4; j++) {
                s[i][j] *= scale;
                if (diag && (k0 + tx * 4 + j) > (q0 + ty * 4 + i))
                    s[i][j] = -INFINITY;
            }

        // Online softmax update
#pragma unroll
        for (int i = 0; i < 4; i++) {
            float rm = s[i][0];
#pragma unroll
            for (int j = 1; j < 4; j++) rm = fmaxf(rm, s[i][j]);
#pragma unroll
            for (int off = 8; off >= 1; off >>= 1)
                rm = fmaxf(rm, __shfl_xor_sync(0xffffffffu, rm, off));
            float mn = fmaxf(m_i[i], rm);
            float corr = __expf(m_i[i] - mn);   // exp(-inf)=0 on first tile
            l_i[i] *= corr;
#pragma unroll
            for (int j = 0; j < 4; j++) O[i][j] *= corr;
            float rs = 0.0f;
#pragma unroll
            for (int j = 0; j < 4; j++) {
                float p = __expf(s[i][j] - mn);
                s[i][j] = p;
                rs += p;
            }
#pragma unroll
            for (int off = 8; off >= 1; off >>= 1)
                rs += __shfl_xor_sync(0xffffffffu, rs, off);
            l_i[i] += rs;
            m_i[i] = mn;
        }

        // Write P, then O += P @ V
#pragma unroll
        for (int i = 0; i < 4; i++)
#pragma unroll
            for (int j = 0; j < 4; j++)
                Ps[(ty * 4 + i) * LD + tx * 4 + j] = s[i][j];
        __syncthreads();

#pragma unroll 8
        for (int c = 0; c < 64; c++) {
            float pv[4], vv[4];
#pragma unroll
            for (int i = 0; i < 4; i++) pv[i] = Ps[(ty * 4 + i) * LD + c];
#pragma unroll
            for (int j = 0; j < 4; j++) vv[j] = Vs[c * LD + tx * 4 + j];
#pragma unroll
            for (int i = 0; i < 4; i++)
#pragma unroll
                for (int j = 0; j < 4; j++) O[i][j] += pv[i] * vv[j];
        }
    }

    // Normalize and write y [B,T,C] with c = h*64 + d
#pragma unroll
    for (int i = 0; i < 4; i++) {
        float inv = 1.0f / l_i[i];
        int t = q0 + ty * 4 + i;
#pragma unroll
        for (int j = 0; j < 4; j++) {
            int d = tx * 4 + j;
            Yout[((size_t)(b_ * TT + t)) * CC + h * DD + d] = O[i][j] * inv;
        }
    }
}

// ---------------------------------------------------------------------------
extern "C" void kernel_launch(void* const* d_in, const int* in_sizes, int n_in,
                              void* d_out, int out_size)
{
    const float* x  = (const float*)d_in[0];   // [B,T,C]
    const float* We = (const float*)d_in[1];   // [3C,C]
    const float* be = (const float*)d_in[2];   // [3C]
    const float* Wp = (const float*)d_in[3];   // [C,C]
    const float* bp = (const float*)d_in[4];   // [C]
    float* out = (float*)d_out;                // [B,T,C]

    // Resolve scratch symbol for flash output (device->device, no alloc)
    float* yPtr = nullptr;
    cudaGetSymbolAddress((void**)&yPtr, g_Y);

    // 1) QKV projection + scatter
    {
        dim3 grid(3 * CC / 64, MROWS / 64);  // (48, 64)
        gemm_bias_kernel<0, 3 * CC, CC><<<grid, 256>>>(x, We, be, nullptr);
    }

    // 2) Flash attention
    {
        const int smem = 4 * 64 * 68 * (int)sizeof(float);  // 69632 B
        cudaFuncSetAttribute(flash_kernel,
                             cudaFuncAttributeMaxDynamicSharedMemorySize, smem);
        dim3 grid(TT / 64, BB * HH);  // (32, 32)
        flash_kernel<<<grid, 256, smem>>>(yPtr);
    }

    // 3) Output projection
    {
        dim3 grid(CC / 64, MROWS / 64);  // (16, 64)
        gemm_bias_kernel<1, CC, CC><<<grid, 256>>>(nullptr, Wp, bp, out);
    }
}

// round 6
// speedup vs baseline: 4.6597x; 4.6597x over previous
#include <cuda_runtime.h>
#include <math.h>
#include <stdint.h>

#define BB 2
#define TT 2048
#define CC 1024
#define HH 16
#define DD 64
#define MROWS (BB*TT)   // 4096

// Scratch (allocation-free rule: __device__ globals)
__device__ float g_Q[BB*HH*TT*DD];   // [B,H,T,D]
__device__ float g_K[BB*HH*TT*DD];
__device__ float g_V[BB*HH*TT*DD];
__device__ float g_Y[BB*TT*CC];      // attention output, [B,T,C]

// ---------------------------------------------------------------------------
// helpers
// ---------------------------------------------------------------------------
__device__ __forceinline__ uint32_t f2t(float x) {
    uint32_t u;
    asm("cvt.rna.tf32.f32 %0, %1;" : "=r"(u) : "f"(x));
    return u;
}

__device__ __forceinline__ void mma8(float* d,
                                     uint32_t a0, uint32_t a1, uint32_t a2, uint32_t a3,
                                     uint32_t b0, uint32_t b1) {
    asm volatile(
        "mma.sync.aligned.m16n8k8.row.col.f32.tf32.tf32.f32 "
        "{%0,%1,%2,%3},{%4,%5,%6,%7},{%8,%9},{%0,%1,%2,%3};"
        : "+f"(d[0]), "+f"(d[1]), "+f"(d[2]), "+f"(d[3])
        : "r"(a0), "r"(a1), "r"(a2), "r"(a3), "r"(b0), "r"(b1));
}

__device__ __forceinline__ void cpa16(void* s, const void* g) {
    uint32_t sa = (uint32_t)__cvta_generic_to_shared(s);
    asm volatile("cp.async.cg.shared.global [%0], [%1], 16;" :: "r"(sa), "l"(g) : "memory");
}

// ---------------------------------------------------------------------------
// TF32 tensor-core GEMM: out[m,n] = sum_k A[m,k]*W[n,k] + bias[n]
// MODE 0: A = input x, scatter into g_Q/g_K/g_V;  MODE 1: A = g_Y, write out.
// CTA tile 128x128, BK=32, 256 threads = 8 warps of 32x64, cp.async 2-stage.
// ---------------------------------------------------------------------------
template<int MODE, int N, int K>
__global__ void __launch_bounds__(256)
gemm_tc(const float* __restrict__ A, const float* __restrict__ W,
        const float* __restrict__ bias, float* __restrict__ out)
{
    extern __shared__ float sm[];
    const int LDA = 36;                    // 32 + 4 pad (conflict-free frags)
    float* As = sm;                        // [2][128][36]
    float* Bs = sm + 2 * 128 * LDA;        // [2][128][36]

    const int bm = blockIdx.y * 128;
    const int bn = blockIdx.x * 128;
    const int tid = threadIdx.x;
    const int wid = tid >> 5, lane = tid & 31;
    const int g = lane >> 2, tg = lane & 3;
    const int wm = (wid & 3) * 32;         // warp m offset in CTA tile
    const int wn = (wid >> 2) * 64;        // warp n offset in CTA tile

    const float* Ap = (MODE == 0) ? A : g_Y;

    float d[2][8][4];
#pragma unroll
    for (int i = 0; i < 2; i++)
#pragma unroll
        for (int j = 0; j < 8; j++)
#pragma unroll
            for (int r = 0; r < 4; r++) d[i][j][r] = 0.0f;

    const int NT = K / 32;

    // tile loader: 1024 16B chunks, 4 per thread (A) + 4 (B)
    auto load_tile = [&](int kt, int buf) {
        const float* Ag = Ap + (size_t)bm * K + kt * 32;
        const float* Wg = W  + (size_t)bn * K + kt * 32;
        float* Ab = As + buf * 128 * LDA;
        float* Bb = Bs + buf * 128 * LDA;
#pragma unroll
        for (int i = 0; i < 4; i++) {
            int c = tid + i * 256;
            int r = c >> 3;
            int col = (c & 7) * 4;
            cpa16(Ab + r * LDA + col, Ag + (size_t)r * K + col);
            cpa16(Bb + r * LDA + col, Wg + (size_t)r * K + col);
        }
        asm volatile("cp.async.commit_group;" ::: "memory");
    };

    load_tile(0, 0);

    for (int kt = 0; kt < NT; kt++) {
        int buf = kt & 1;
        if (kt + 1 < NT) {
            load_tile(kt + 1, buf ^ 1);
            asm volatile("cp.async.wait_group 1;" ::: "memory");
        } else {
            asm volatile("cp.async.wait_group 0;" ::: "memory");
        }
        __syncthreads();

        const float* Ab = As + buf * 128 * LDA;
        const float* Bb = Bs + buf * 128 * LDA;

#pragma unroll
        for (int ks = 0; ks < 4; ks++) {
            int k = ks * 8;
            uint32_t a[2][4], b[8][2];
#pragma unroll
            for (int am = 0; am < 2; am++) {
                const float* base = Ab + (wm + am * 16 + g) * LDA + k + tg;
                a[am][0] = f2t(base[0]);
                a[am][1] = f2t(base[8 * LDA]);
                a[am][2] = f2t(base[4]);
                a[am][3] = f2t(base[8 * LDA + 4]);
            }
#pragma unroll
            for (int bj = 0; bj < 8; bj++) {
                const float* base = Bb + (wn + bj * 8 + g) * LDA + k + tg;
                b[bj][0] = f2t(base[0]);
                b[bj][1] = f2t(base[4]);
            }
#pragma unroll
            for (int am = 0; am < 2; am++)
#pragma unroll
                for (int bj = 0; bj < 8; bj++)
                    mma8(d[am][bj], a[am][0], a[am][1], a[am][2], a[am][3],
                         b[bj][0], b[bj][1]);
        }
        __syncthreads();
    }

    // epilogue
#pragma unroll
    for (int am = 0; am < 2; am++) {
#pragma unroll
        for (int bj = 0; bj < 8; bj++) {
#pragma unroll
            for (int r = 0; r < 4; r++) {
                int row = bm + wm + am * 16 + g + (r >> 1) * 8;
                int col = bn + wn + bj * 8 + tg * 2 + (r & 1);
                float v = d[am][bj][r] + bias[col];
                if (MODE == 0) {
                    int part = col / CC;
                    int c    = col - part * CC;
                    int hh   = c >> 6;
                    int dd   = c & 63;
                    int b_   = row / TT;
                    int t    = row - b_ * TT;
                    int idx  = ((b_ * HH + hh) * TT + t) * DD + dd;
                    if (part == 0)      g_Q[idx] = v;
                    else if (part == 1) g_K[idx] = v;
                    else                g_V[idx] = v;
                } else {
                    out[(size_t)row * N + col] = v;
                }
            }
        }
    }
}

// ---------------------------------------------------------------------------
// Flash attention, tf32 tensor cores. Block = 64 q rows, one (b,h).
// 128 threads = 4 warps; warp w owns rows 16w..16w+15 (one m16 atom).
// ---------------------------------------------------------------------------
__global__ void __launch_bounds__(128)
flash_tc(float* __restrict__ Yout)
{
    extern __shared__ float sm[];
    float* Qs = sm;                  // 64 x 68  (tf32, pre-scaled by 0.125)
    float* Ks = Qs + 64 * 68;        // 64 x 68
    float* Vs = Ks + 64 * 68;        // 64 x 72
    float* Ps = Vs + 64 * 72;        // 64 x 68 (warp-private 16-row slabs)

    const int qt = blockIdx.x;
    const int bh = blockIdx.y;
    const int b_ = bh / HH;
    const int h  = bh % HH;
    const int q0 = qt * 64;

    const float* Qg = g_Q + (size_t)bh * TT * DD;
    const float* Kg = g_K + (size_t)bh * TT * DD;
    const float* Vg = g_V + (size_t)bh * TT * DD;

    const int tid = threadIdx.x;
    const int w = tid >> 5, lane = tid & 31;
    const int g = lane >> 2, tg = lane & 3;

    // Load Q tile, fold 1/sqrt(64)=0.125 (exact), convert to tf32
    for (int i = tid; i < 64 * 16; i += 128) {
        int r = i >> 4, c = (i & 15) * 4;
        float4 q = *(const float4*)(Qg + (size_t)(q0 + r) * DD + c);
        float4 o;
        o.x = __uint_as_float(f2t(q.x * 0.125f));
        o.y = __uint_as_float(f2t(q.y * 0.125f));
        o.z = __uint_as_float(f2t(q.z * 0.125f));
        o.w = __uint_as_float(f2t(q.w * 0.125f));
        *(float4*)(Qs + r * 68 + c) = o;
    }

    const int row0l = 16 * w + g;
    const int row1l = row0l + 8;
    const int row0 = q0 + row0l;
    const int row1 = q0 + row1l;

    float m0 = -INFINITY, m1 = -INFINITY, l0 = 0.0f, l1 = 0.0f;
    float O[8][4];
#pragma unroll
    for (int i = 0; i < 8; i++)
#pragma unroll
        for (int r = 0; r < 4; r++) O[i][r] = 0.0f;

    for (int kt = 0; kt <= qt; kt++) {
        const int k0 = kt * 64;
        __syncthreads();
        for (int i = tid; i < 64 * 16; i += 128) {
            int r = i >> 4, c = (i & 15) * 4;
            float4 kk = *(const float4*)(Kg + (size_t)(k0 + r) * DD + c);
            float4 vv = *(const float4*)(Vg + (size_t)(k0 + r) * DD + c);
            float4 ok, ov;
            ok.x = __uint_as_float(f2t(kk.x)); ok.y = __uint_as_float(f2t(kk.y));
            ok.z = __uint_as_float(f2t(kk.z)); ok.w = __uint_as_float(f2t(kk.w));
            ov.x = __uint_as_float(f2t(vv.x)); ov.y = __uint_as_float(f2t(vv.y));
            ov.z = __uint_as_float(f2t(vv.z)); ov.w = __uint_as_float(f2t(vv.w));
            *(float4*)(Ks + r * 68 + c) = ok;
            *(float4*)(Vs + r * 72 + c) = ov;
        }
        __syncthreads();

        // S = Q K^T  (Q pre-scaled)
        float s[8][4];
#pragma unroll
        for (int i = 0; i < 8; i++)
#pragma unroll
            for (int r = 0; r < 4; r++) s[i][r] = 0.0f;

#pragma unroll
        for (int ks = 0; ks < 8; ks++) {
            int k = ks * 8;
            const float* qb = Qs + row0l * 68 + k + tg;
            uint32_t a0 = __float_as_uint(qb[0]);
            uint32_t a1 = __float_as_uint(qb[8 * 68]);
            uint32_t a2 = __float_as_uint(qb[4]);
            uint32_t a3 = __float_as_uint(qb[8 * 68 + 4]);
#pragma unroll
            for (int bn = 0; bn < 8; bn++) {
                const float* kb = Ks + (bn * 8 + g) * 68 + k + tg;
                mma8(s[bn], a0, a1, a2, a3,
                     __float_as_uint(kb[0]), __float_as_uint(kb[4]));
            }
        }

        // mask + online softmax
        const bool diag = (kt == qt);
        float rm0 = -INFINITY, rm1 = -INFINITY;
#pragma unroll
        for (int bn = 0; bn < 8; bn++) {
            if (diag) {
                int cb = k0 + bn * 8 + tg * 2;
                if (cb     > row0) s[bn][0] = -INFINITY;
                if (cb + 1 > row0) s[bn][1] = -INFINITY;
                if (cb     > row1) s[bn][2] = -INFINITY;
                if (cb + 1 > row1) s[bn][3] = -INFINITY;
            }
            rm0 = fmaxf(rm0, fmaxf(s[bn][0], s[bn][1]));
            rm1 = fmaxf(rm1, fmaxf(s[bn][2], s[bn][3]));
        }
        rm0 = fmaxf(rm0, __shfl_xor_sync(0xffffffffu, rm0, 1));
        rm0 = fmaxf(rm0, __shfl_xor_sync(0xffffffffu, rm0, 2));
        rm1 = fmaxf(rm1, __shfl_xor_sync(0xffffffffu, rm1, 1));
        rm1 = fmaxf(rm1, __shfl_xor_sync(0xffffffffu, rm1, 2));

        float mn0 = fmaxf(m0, rm0), mn1 = fmaxf(m1, rm1);
        float c0 = __expf(m0 - mn0), c1 = __expf(m1 - mn1);
        l0 *= c0; l1 *= c1;
#pragma unroll
        for (int bn = 0; bn < 8; bn++) {
            O[bn][0] *= c0; O[bn][1] *= c0;
            O[bn][2] *= c1; O[bn][3] *= c1;
        }

        float rs0 = 0.0f, rs1 = 0.0f;
        float* Pw = Ps + 16 * w * 68;       // warp-private 16x68 slab
#pragma unroll
        for (int bn = 0; bn < 8; bn++) {
            float p0 = __expf(s[bn][0] - mn0);
            float p1 = __expf(s[bn][1] - mn0);
            float p2 = __expf(s[bn][2] - mn1);
            float p3 = __expf(s[bn][3] - mn1);
            rs0 += p0 + p1; rs1 += p2 + p3;
            int cc = bn * 8 + tg * 2;
            Pw[g * 68 + cc]           = __uint_as_float(f2t(p0));
            Pw[g * 68 + cc + 1]       = __uint_as_float(f2t(p1));
            Pw[(g + 8) * 68 + cc]     = __uint_as_float(f2t(p2));
            Pw[(g + 8) * 68 + cc + 1] = __uint_as_float(f2t(p3));
        }
        rs0 += __shfl_xor_sync(0xffffffffu, rs0, 1);
        rs0 += __shfl_xor_sync(0xffffffffu, rs0, 2);
        rs1 += __shfl_xor_sync(0xffffffffu, rs1, 1);
        rs1 += __shfl_xor_sync(0xffffffffu, rs1, 2);
        l0 += rs0; l1 += rs1;
        m0 = mn0; m1 = mn1;

        __syncwarp();   // P visible within the warp

        // O += P @ V
#pragma unroll
        for (int ks = 0; ks < 8; ks++) {
            int k = ks * 8;
            const float* pb = Pw + g * 68 + k + tg;
            uint32_t a0 = __float_as_uint(pb[0]);
            uint32_t a1 = __float_as_uint(pb[8 * 68]);
            uint32_t a2 = __float_as_uint(pb[4]);
            uint32_t a3 = __float_as_uint(pb[8 * 68 + 4]);
#pragma unroll
            for (int bn = 0; bn < 8; bn++) {
                const float* vb = Vs + (k + tg) * 72 + bn * 8 + g;
                mma8(O[bn], a0, a1, a2, a3,
                     __float_as_uint(vb[0]), __float_as_uint(vb[4 * 72]));
            }
        }
    }

    // normalize + write y [B,T,C], c = h*64 + d
    float inv0 = 1.0f / l0, inv1 = 1.0f / l1;
    float* yr0 = Yout + ((size_t)(b_ * TT + row0)) * CC + h * DD;
    float* yr1 = Yout + ((size_t)(b_ * TT + row1)) * CC + h * DD;
#pragma unroll
    for (int bn = 0; bn < 8; bn++) {
        int cc = bn * 8 + tg * 2;
        yr0[cc]     = O[bn][0] * inv0;
        yr0[cc + 1] = O[bn][1] * inv0;
        yr1[cc]     = O[bn][2] * inv1;
        yr1[cc + 1] = O[bn][3] * inv1;
    }
}

// ---------------------------------------------------------------------------
extern "C" void kernel_launch(void* const* d_in, const int* in_sizes, int n_in,
                              void* d_out, int out_size)
{
    const float* x  = (const float*)d_in[0];   // [B,T,C]
    const float* We = (const float*)d_in[1];   // [3C,C]
    const float* be = (const float*)d_in[2];   // [3C]
    const float* Wp = (const float*)d_in[3];   // [C,C]
    const float* bp = (const float*)d_in[4];   // [C]
    float* out = (float*)d_out;                // [B,T,C]

    float* yPtr = nullptr;
    cudaGetSymbolAddress((void**)&yPtr, g_Y);

    const int gemm_smem = 2 * 2 * 128 * 36 * (int)sizeof(float);  // 73728
    const int flash_smem = (64 * 68 * 3 + 64 * 72) * (int)sizeof(float); // 70656

    // 1) QKV projection + scatter  (M=4096, N=3072, K=1024)
    {
        cudaFuncSetAttribute(gemm_tc<0, 3 * CC, CC>,
                             cudaFuncAttributeMaxDynamicSharedMemorySize, gemm_smem);
        dim3 grid(3 * CC / 128, MROWS / 128);  // (24, 32)
        gemm_tc<0, 3 * CC, CC><<<grid, 256, gemm_smem>>>(x, We, be, nullptr);
    }

    // 2) Flash attention
    {
        cudaFuncSetAttribute(flash_tc,
                             cudaFuncAttributeMaxDynamicSharedMemorySize, flash_smem);
        dim3 grid(TT / 64, BB * HH);  // (32, 32)
        flash_tc<<<grid, 128, flash_smem>>>(yPtr);
    }

    // 3) Output projection  (M=4096, N=1024, K=1024)
    {
        cudaFuncSetAttribute(gemm_tc<1, CC, CC>,
                             cudaFuncAttributeMaxDynamicSharedMemorySize, gemm_smem);
        dim3 grid(CC / 128, MROWS / 128);  // (8, 32)
        gemm_tc<1, CC, CC><<<grid, 256, gemm_smem>>>(nullptr, Wp, bp, out);
    }
}